// round 1
// baseline (speedup 1.0000x reference)
#include <cuda_runtime.h>

// Problem constants (fixed by the dataset)
#define HG   256
#define WG   256
#define BB   2
#define CC   4
#define NN   1024
#define TILE 8                 // 8x8 grid cells per CTA
#define TPB  64                // one thread per cell
#define TILES_X (WG / TILE)    // 32
#define TILES_Y (HG / TILE)    // 32

// half-diagonal of an 8x8-cell tile: (TILE/2)/256 * sqrt(2)
#define RT 0.0220970869f

__global__ __launch_bounds__(TPB)
void nn_tile_kernel(const float* __restrict__ R_pc,   // [B, C, N]
                    const float* __restrict__ XY_pc,  // [B, 2, N]
                    float* __restrict__ out)          // [B, C, H, W]
{
    __shared__ float4 sv[NN];      // surviving points: (px, py, pn2, idx-bits)
    __shared__ int    s_cnt;
    __shared__ float  s_warpmin[TPB / 32];

    const int tile = blockIdx.x;           // 0..1023
    const int b    = blockIdx.y;           // 0..1
    const int tj   = tile % TILES_X;
    const int ti   = tile / TILES_X;
    const int t    = threadIdx.x;

    const float inv = 1.0f / 256.0f;
    const float cx  = (float)(tj * TILE + TILE / 2) * inv;  // tile center
    const float cy  = (float)(ti * TILE + TILE / 2) * inv;

    const float* Xb = XY_pc + b * 2 * NN;

    // ---- Phase 1: min distance^2 from tile center to any point ----
    float dmin = 3.4e38f;
    #pragma unroll 4
    for (int n = t; n < NN; n += TPB) {
        float px = Xb[n];
        float py = Xb[NN + n];
        float dx = px - cx, dy = py - cy;
        float d2 = fmaf(dx, dx, dy * dy);
        dmin = fminf(dmin, d2);
    }
    #pragma unroll
    for (int o = 16; o > 0; o >>= 1)
        dmin = fminf(dmin, __shfl_xor_sync(0xffffffffu, dmin, o));
    if ((t & 31) == 0) s_warpmin[t >> 5] = dmin;
    if (t == 0) s_cnt = 0;
    __syncthreads();

    float rmin = fminf(s_warpmin[0], s_warpmin[1]);
    // cull radius: r_min + 2*r_tile (+ fp safety margin). Exact bound:
    // any point farther from the center cannot be nearest for any cell here.
    float Rrad = sqrtf(rmin) + 2.0f * RT + 1e-3f;
    float R2   = Rrad * Rrad;

    // ---- Phase 2: compact survivors into shared memory ----
    #pragma unroll 4
    for (int n = t; n < NN; n += TPB) {
        float px = Xb[n];
        float py = Xb[NN + n];
        float dx = px - cx, dy = py - cy;
        float d2 = fmaf(dx, dx, dy * dy);
        if (d2 <= R2) {
            int slot = atomicAdd(&s_cnt, 1);
            // pn2 matches reference: round(px*px) + round(py*py), no fma
            float pn2 = __fadd_rn(__fmul_rn(px, px), __fmul_rn(py, py));
            sv[slot] = make_float4(px, py, pn2, __int_as_float(n));
        }
    }
    __syncthreads();
    const int M = s_cnt;

    // ---- Phase 3: per-cell argmin over survivors ----
    const int jl = t & (TILE - 1);
    const int il = t >> 3;
    const int gi = ti * TILE + il;
    const int gj = tj * TILE + jl;
    const float gx = ((float)gj + 0.5f) * inv;
    const float gy = ((float)gi + 0.5f) * inv;

    float best  = 3.4e38f;
    int   bestN = 0;
    for (int m = 0; m < M; m++) {
        float4 p  = sv[m];
        // mirror reference: dot = fma(gy*py, round(gx*px)); d2 = pn2 - 2*dot
        float dot = fmaf(gy, p.y, __fmul_rn(gx, p.x));
        float d2  = __fadd_rn(p.z, -2.0f * dot);
        int   n   = __float_as_int(p.w);
        // order-independent argmin with first-index tie-break (matches jnp.argmin)
        if (d2 < best || (d2 == best && n < bestN)) {
            best  = d2;
            bestN = n;
        }
    }

    // ---- Gather channel values and write output ----
    const float* Rb = R_pc + b * CC * NN;
    float* ob = out + ((size_t)b * CC * HG * WG) + (size_t)gi * WG + gj;
    #pragma unroll
    for (int c = 0; c < CC; c++)
        ob[(size_t)c * HG * WG] = Rb[c * NN + bestN];
}

extern "C" void kernel_launch(void* const* d_in, const int* in_sizes, int n_in,
                              void* d_out, int out_size)
{
    (void)in_sizes; (void)n_in; (void)out_size;
    const float* R_pc  = (const float*)d_in[0];  // [2,4,1024]
    const float* XY_pc = (const float*)d_in[1];  // [2,2,1024]
    float* out = (float*)d_out;                  // [2,4,256,256]

    dim3 grid(TILES_X * TILES_Y, BB);
    nn_tile_kernel<<<grid, TPB>>>(R_pc, XY_pc, out);
}

// round 3
// speedup vs baseline: 1.2362x; 1.2362x over previous
#include <cuda_runtime.h>

// Problem constants (fixed by the dataset)
#define HG   256
#define WG   256
#define BB   2
#define CC   4
#define NN   1024
#define TILE 16                // 16x16 grid cells per CTA
#define TPB  256               // one thread per cell
#define TILES_X (WG / TILE)    // 16
#define TILES_Y (HG / TILE)    // 16
#define PPT  (NN / TPB)        // 4 points per thread
#define CAP  512               // survivor capacity (expected ~36)

// half-diagonal of a 16x16-cell tile: (TILE/2)/256 * sqrt(2)
#define RT 0.0441941738f

__global__ __launch_bounds__(TPB)
void nn_tile_kernel(const float* __restrict__ R_pc,   // [B, C, N]
                    const float* __restrict__ XY_pc,  // [B, 2, N]
                    float* __restrict__ out)          // [B, C, H, W]
{
    __shared__ float4 sv[CAP];     // surviving points: (px, py, pn2, idx-bits)
    __shared__ int    s_cnt;
    __shared__ float  s_warpmin[TPB / 32];

    const int tile = blockIdx.x;           // 0..255
    const int b    = blockIdx.y;           // 0..1
    const int tj   = tile % TILES_X;
    const int ti   = tile / TILES_X;
    const int t    = threadIdx.x;

    const float inv = 1.0f / 256.0f;
    const float cx  = (float)(tj * TILE + TILE / 2) * inv;  // tile center
    const float cy  = (float)(ti * TILE + TILE / 2) * inv;

    const float* Xb = XY_pc + b * 2 * NN;

    // ---- Load 4 points per thread ONCE (two LDG.128), keep in registers ----
    const int nbase = t * PPT;
    float4 px4 = *(const float4*)(Xb + nbase);
    float4 py4 = *(const float4*)(Xb + NN + nbase);
    float px[PPT] = {px4.x, px4.y, px4.z, px4.w};
    float py[PPT] = {py4.x, py4.y, py4.z, py4.w};

    // ---- Phase 1: min distance^2 from tile center (register data) ----
    float d2c[PPT];
    float dmin = 3.4e38f;
    #pragma unroll
    for (int k = 0; k < PPT; k++) {
        float dx = px[k] - cx, dy = py[k] - cy;
        d2c[k] = fmaf(dx, dx, dy * dy);
        dmin = fminf(dmin, d2c[k]);
    }
    #pragma unroll
    for (int o = 16; o > 0; o >>= 1)
        dmin = fminf(dmin, __shfl_xor_sync(0xffffffffu, dmin, o));
    if ((t & 31) == 0) s_warpmin[t >> 5] = dmin;
    if (t == 0) s_cnt = 0;
    __syncthreads();

    float rmin = s_warpmin[0];
    #pragma unroll
    for (int w = 1; w < TPB / 32; w++) rmin = fminf(rmin, s_warpmin[w]);

    // cull radius: r_min + 2*r_tile (+ fp safety margin). Exact bound:
    // a point farther from the center cannot be nearest for any cell here.
    float Rrad = sqrtf(rmin) + 2.0f * RT + 1e-3f;
    float R2   = Rrad * Rrad;

    // ---- Phase 2: compact survivors into shared memory (from registers) ----
    #pragma unroll
    for (int k = 0; k < PPT; k++) {
        if (d2c[k] <= R2) {
            int slot = atomicAdd(&s_cnt, 1);
            if (slot < CAP) {
                // pn2 matches reference: round(px*px) + round(py*py), no fma
                float pn2 = __fadd_rn(__fmul_rn(px[k], px[k]),
                                      __fmul_rn(py[k], py[k]));
                sv[slot] = make_float4(px[k], py[k], pn2,
                                       __int_as_float(nbase + k));
            }
        }
    }
    __syncthreads();
    const int M = s_cnt;

    // ---- Phase 3: per-cell argmin ----
    const int jl = t & (TILE - 1);
    const int il = t >> 4;
    const int gi = ti * TILE + il;
    const int gj = tj * TILE + jl;
    const float gx = ((float)gj + 0.5f) * inv;
    const float gy = ((float)gi + 0.5f) * inv;

    float best  = 3.4e38f;
    int   bestN = 0;

    if (M <= CAP) {
        for (int m = 0; m < M; m++) {
            float4 p  = sv[m];
            // mirror reference: dot = fma(gy,py, gx*px); d2 = pn2 - 2*dot
            float dot = fmaf(gy, p.y, __fmul_rn(gx, p.x));
            float d2  = __fadd_rn(p.z, -2.0f * dot);
            int   n   = __float_as_int(p.w);
            // order-independent argmin, first-index tie-break (jnp.argmin rule)
            if (d2 < best || (d2 == best && n < bestN)) {
                best  = d2;
                bestN = n;
            }
        }
    } else {
        // overflow fallback (never expected for this dataset): full scan
        for (int n = 0; n < NN; n++) {
            float qx = Xb[n], qy = Xb[NN + n];
            float pn2 = __fadd_rn(__fmul_rn(qx, qx), __fmul_rn(qy, qy));
            float dot = fmaf(gy, qy, __fmul_rn(gx, qx));
            float d2  = __fadd_rn(pn2, -2.0f * dot);
            if (d2 < best || (d2 == best && n < bestN)) {
                best  = d2;
                bestN = n;
            }
        }
    }

    // ---- Gather channel values and write output ----
    const float* Rb = R_pc + b * CC * NN;
    float* ob = out + ((size_t)b * CC * HG * WG) + (size_t)gi * WG + gj;
    #pragma unroll
    for (int c = 0; c < CC; c++)
        ob[(size_t)c * HG * WG] = Rb[c * NN + bestN];
}

extern "C" void kernel_launch(void* const* d_in, const int* in_sizes, int n_in,
                              void* d_out, int out_size)
{
    (void)in_sizes; (void)n_in; (void)out_size;
    const float* R_pc  = (const float*)d_in[0];  // [2,4,1024]
    const float* XY_pc = (const float*)d_in[1];  // [2,2,1024]
    float* out = (float*)d_out;                  // [2,4,256,256]

    dim3 grid(TILES_X * TILES_Y, BB);
    nn_tile_kernel<<<grid, TPB>>>(R_pc, XY_pc, out);
}